// round 6
// baseline (speedup 1.0000x reference)
#include <cuda_runtime.h>

// NeRF fine sampling + merge. TWO rays per warp (16 lanes x 8 elements each).
// SC=64 sorted coarse dists, 63 weights, SF=128 fine samples, out 192 sorted.
#define SC   64
#define SF   128
#define NOUT 192
#define WPB  8
#define FULL 0xffffffffu

__device__ __forceinline__ void ce(float& x, float& y, bool asc) {
    float lo = fminf(x, y), hi = fmaxf(x, y);
    x = asc ? lo : hi;
    y = asc ? hi : lo;
}

__global__ __launch_bounds__(32 * WPB, 4)
void fine_sample_kernel(const float* __restrict__ dists,
                        const float* __restrict__ weights,
                        const float* __restrict__ rands,
                        float* __restrict__ out, int B)
{
    __shared__ __align__(16) float  cdfs_s[WPB][2][68];  // cdf[0..63], stride-4B probes
    __shared__ __align__(16) float4 quad_s[WPB][2][64];  // (cdf[i],cdf[i+1],d[i],d[i+1])
    __shared__ __align__(16) int    pref_s[WPB][2][64];  // first-rank-per-bin
    __shared__ __align__(16) float  out_s[WPB][2][NOUT];

    const int wid  = threadIdx.x >> 5;
    const int lane = threadIdx.x & 31;
    const int half = lane >> 4;         // which ray in the warp
    const int hl   = lane & 15;         // lane within ray
    const int base = (blockIdx.x * WPB + wid) * 2;
    const int ray  = base + half;
    if (ray >= B) return;

    float*  cdfs = cdfs_s[wid][half];
    float4* quad = quad_s[wid][half];
    int*    pref = pref_s[wid][half];
    float*  obf  = out_s[wid][half];

    // pref default: "no sample has bin >= j" -> 128
    ((int4*)pref)[hl] = make_int4(128, 128, 128, 128);

    // ---- loads (all vectorized) ----
    const float4* dptr4 = (const float4*)(dists + (size_t)ray * SC);
    float4 dd = dptr4[hl];                               // d[4hl..4hl+3]
    const float* wptr = weights + (size_t)ray * (SC - 1);
    int wi = 4 * hl;
    float w0 = wptr[wi]     + 0.01f;
    float w1 = wptr[wi + 1] + 0.01f;
    float w2 = wptr[wi + 2] + 0.01f;
    float w3 = (hl < 15) ? (wptr[wi + 3] + 0.01f) : 0.0f;

    // ---- scan (width 16, both rays in parallel) ----
    float c1 = w0, c2 = c1 + w1, c3 = c2 + w2;
    float e  = c3 + w3;
    float E = e;
    #pragma unroll
    for (int off = 1; off < 16; off <<= 1) {
        float t = __shfl_up_sync(FULL, E, off);
        if (hl >= off) E += t;
    }
    const int hb = half << 4;
    float total = __shfl_sync(FULL, E, hb | 15);
    float inv = 1.0f / total;
    float c0e = E - e;                                   // exclusive prefix
    float4 cv = make_float4(c0e * inv, (c0e + c1) * inv,
                            (c0e + c2) * inv, (c0e + c3) * inv);  // cdf[4hl..4hl+3]
    ((float4*)cdfs)[hl] = cv;

    // register probes cdf[8|16|24|32|40|48|56]
    float c8  = __shfl_sync(FULL, E, hb | 1)  * inv;
    float c16 = __shfl_sync(FULL, E, hb | 3)  * inv;
    float c24 = __shfl_sync(FULL, E, hb | 5)  * inv;
    float c32 = __shfl_sync(FULL, E, hb | 7)  * inv;
    float c40 = __shfl_sync(FULL, E, hb | 9)  * inv;
    float c48 = __shfl_sync(FULL, E, hb | 11) * inv;
    float c56 = __shfl_sync(FULL, E, hb | 13) * inv;

    // ---- quad table ----
    float dnext = __shfl_down_sync(FULL, dd.x, 1);
    if (hl == 15) dnext = dd.w;                          // d[64] sentinel = d[63]
    float ctop = E * inv;                                // cdf[4hl+4] (hl=15 -> 1.0)
    quad[wi]     = make_float4(cv.x, cv.y, dd.x, dd.y);
    quad[wi + 1] = make_float4(cv.y, cv.z, dd.y, dd.z);
    quad[wi + 2] = make_float4(cv.z, cv.w, dd.z, dd.w);
    quad[wi + 3] = make_float4(cv.w, ctop, dd.w, dnext);

    // ---- load 8 u's (element index i = hl*8 + m) ----
    const float4* up4 = (const float4*)(rands + (size_t)ray * SF);
    float4 ua = up4[2 * hl], ub = up4[2 * hl + 1];
    float k[8] = {ua.x, ua.y, ua.z, ua.w, ub.x, ub.y, ub.z, ub.w};

    // ---- bitonic sort of 128 u's across 16 lanes x 8 regs ----
    // k=2
    ce(k[0], k[1], true);  ce(k[2], k[3], false);
    ce(k[4], k[5], true);  ce(k[6], k[7], false);
    // k=4
    ce(k[0], k[2], true);  ce(k[1], k[3], true);
    ce(k[0], k[1], true);  ce(k[2], k[3], true);
    ce(k[4], k[6], false); ce(k[5], k[7], false);
    ce(k[4], k[5], false); ce(k[6], k[7], false);
    // k=8 (fully intra-lane)
    {
        bool a = (hl & 1) == 0;
        ce(k[0], k[4], a); ce(k[1], k[5], a); ce(k[2], k[6], a); ce(k[3], k[7], a);
        ce(k[0], k[2], a); ce(k[1], k[3], a); ce(k[4], k[6], a); ce(k[5], k[7], a);
        ce(k[0], k[1], a); ce(k[2], k[3], a); ce(k[4], k[5], a); ce(k[6], k[7], a);
    }
    // k=16..128
    #pragma unroll
    for (int kk = 16; kk <= 128; kk <<= 1) {
        bool a = (hl & (kk >> 3)) == 0;          // (i & kk)==0, i = hl*8+m
        #pragma unroll
        for (int L = kk >> 4; L >= 1; L >>= 1) { // lane distance = j/8, stays in half
            bool dm = (((hl & L) == 0) == a);
            #pragma unroll
            for (int m = 0; m < 8; m++) {
                float p = __shfl_xor_sync(FULL, k[m], L);
                k[m] = dm ? fminf(k[m], p) : fmaxf(k[m], p);
            }
        }
        ce(k[0], k[4], a); ce(k[1], k[5], a); ce(k[2], k[6], a); ce(k[3], k[7], a);
        ce(k[0], k[2], a); ce(k[1], k[3], a); ce(k[4], k[6], a); ce(k[5], k[7], a);
        ce(k[0], k[1], a); ce(k[2], k[3], a); ce(k[4], k[5], a); ce(k[6], k[7], a);
    }
    __syncwarp();   // cdfs/quad tables ready

    // ---- search + interp on SORTED u's; scatter samples; first-occurrence ----
    int prev = -1, idx0 = 0;
    #pragma unroll
    for (int m = 0; m < 8; m++) {
        float u = k[m];
        int idx = (c32 <= u) ? 32 : 0;
        float p2 = idx ? c48 : c16;
        if (p2 <= u) idx += 16;
        float p3 = (idx & 32) ? ((idx & 16) ? c56 : c40)
                              : ((idx & 16) ? c24 : c8);
        if (p3 <= u) idx += 8;
        if (cdfs[idx + 4] <= u) idx += 4;
        if (cdfs[idx + 2] <= u) idx += 2;
        if (cdfs[idx + 1] <= u) idx += 1;
        float4 q = quad[idx];
        float den = q.y - q.x;
        den = (den < 1e-5f) ? 1.0f : den;
        float t = (u - q.x) / den;
        float s = fmaf(t, q.w - q.z, q.z);
        s = fminf(s, q.w);                       // keep keys bin-monotone
        obf[hl * 8 + m + idx + 1] = s;           // pos = rank + bin + 1
        if (m == 0) idx0 = idx;
        else if (idx != prev) pref[idx] = hl * 8 + m;
        prev = idx;
    }
    int pb = __shfl_up_sync(FULL, prev, 1);      // prev holds idx of m=7
    if (hl == 0) pb = -1;
    if (idx0 != pb) pref[idx0] = hl * 8;
    __syncwarp();

    // ---- suffix-min over pref[0..63] (4 per lane) ----
    int4 P = ((int4*)pref)[hl];
    int s3 = P.w;
    int s2 = min(P.z, s3);
    int s1 = min(P.y, s2);
    int s0 = min(P.x, s1);
    int S = s0;
    #pragma unroll
    for (int off = 1; off < 16; off <<= 1) {
        int t = __shfl_down_sync(FULL, S, off);
        if (hl + off < 16) S = min(S, t);
    }
    int Sn = __shfl_down_sync(FULL, S, 1);
    if (hl == 15) Sn = 128;
    int f3 = min(s3, Sn);
    int f2 = min(s2, f3);
    int f1 = min(s1, f2);
    int f0 = min(s0, f1);

    // ---- dists: pos = j + prefix[j] ----
    obf[wi     + f0] = dd.x;
    obf[wi + 1 + f1] = dd.y;
    obf[wi + 2 + f2] = dd.z;
    obf[wi + 3 + f3] = dd.w;
    __syncwarp();

    // ---- coalesced vectorized output (both rays contiguous) ----
    const float4* ob4 = (const float4*)out_s[wid][0];
    float4* op4 = (float4*)(out + (size_t)base * NOUT);
    #pragma unroll
    for (int t = 0; t < 3; t++)
        op4[t * 32 + lane] = ob4[t * 32 + lane];
}

extern "C" void kernel_launch(void* const* d_in, const int* in_sizes, int n_in,
                              void* d_out, int out_size) {
    const float* dists   = (const float*)d_in[0];
    const float* weights = (const float*)d_in[1];
    const float* rands   = (const float*)d_in[2];
    float* out = (float*)d_out;
    int B = in_sizes[0] / SC;
    int raysPerBlock = 2 * WPB;
    int blocks = (B + raysPerBlock - 1) / raysPerBlock;
    fine_sample_kernel<<<blocks, 32 * WPB>>>(dists, weights, rands, out, B);
}

// round 7
// speedup vs baseline: 1.0898x; 1.0898x over previous
#include <cuda_runtime.h>

// NeRF fine sampling + merge. TWO rays per warp (16 lanes x 8 elements each).
// Scalar/float2 shared-memory data path (R5-style), R6 sort topology.
#define SC   64
#define SF   128
#define NOUT 192
#define WPB  8
#define FULL 0xffffffffu

__device__ __forceinline__ void ce(float& x, float& y, bool asc) {
    float lo = fminf(x, y), hi = fmaxf(x, y);
    x = asc ? lo : hi;
    y = asc ? hi : lo;
}

__global__ __launch_bounds__(32 * WPB, 4)
void fine_sample_kernel(const float* __restrict__ dists,
                        const float* __restrict__ weights,
                        const float* __restrict__ rands,
                        float* __restrict__ out, int B)
{
    __shared__ __align__(16) float  cdfs_s[WPB][2][68];  // scalar cdf[0..64] for probes
    __shared__ __align__(16) float2 pair_s[WPB][2][66];  // (cdf[i], d[i]), i=0..64
    __shared__ __align__(16) int    pref_s[WPB][2][64];  // first-rank-per-bin
    __shared__ __align__(16) float  out_s[WPB][2][NOUT];

    const int wid  = threadIdx.x >> 5;
    const int lane = threadIdx.x & 31;
    const int half = lane >> 4;
    const int hl   = lane & 15;
    const int base = (blockIdx.x * WPB + wid) * 2;
    const int ray  = base + half;
    if (ray >= B) return;

    float*  cdfs = cdfs_s[wid][half];
    float2* pair = pair_s[wid][half];
    int*    pref = pref_s[wid][half];
    float*  obf  = out_s[wid][half];

    // pref default: 128
    ((int4*)pref)[hl] = make_int4(128, 128, 128, 128);

    // ---- loads ----
    const float4* dptr4 = (const float4*)(dists + (size_t)ray * SC);
    float4 dd = dptr4[hl];                               // d[4hl..4hl+3]
    const float* wptr = weights + (size_t)ray * (SC - 1);
    const int wi = 4 * hl;
    float w0 = wptr[wi]     + 0.01f;
    float w1 = wptr[wi + 1] + 0.01f;
    float w2 = wptr[wi + 2] + 0.01f;
    float w3 = (hl < 15) ? (wptr[wi + 3] + 0.01f) : 0.0f;

    // ---- scan (width 16, both rays in parallel) ----
    float p1 = w0, p2 = p1 + w1, p3 = p2 + w2;
    float e  = p3 + w3;
    float E = e;
    #pragma unroll
    for (int off = 1; off < 16; off <<= 1) {
        float t = __shfl_up_sync(FULL, E, off);
        if (hl >= off) E += t;
    }
    const int hb = half << 4;
    float total = __shfl_sync(FULL, E, hb | 15);
    float inv = 1.0f / total;
    float c0e = E - e;
    float4 cv = make_float4(c0e * inv, (c0e + p1) * inv,
                            (c0e + p2) * inv, (c0e + p3) * inv);  // cdf[4hl..4hl+3]
    ((float4*)cdfs)[hl] = cv;
    if (hl == 15) cdfs[64] = 1.0f;

    // register probes cdf[8|16|24|32|40|48|56]
    float c8  = __shfl_sync(FULL, E, hb | 1)  * inv;
    float c16 = __shfl_sync(FULL, E, hb | 3)  * inv;
    float c24 = __shfl_sync(FULL, E, hb | 5)  * inv;
    float c32 = __shfl_sync(FULL, E, hb | 7)  * inv;
    float c40 = __shfl_sync(FULL, E, hb | 9)  * inv;
    float c48 = __shfl_sync(FULL, E, hb | 11) * inv;
    float c56 = __shfl_sync(FULL, E, hb | 13) * inv;

    // ---- (cdf,d) pair table, contiguous STS.128 ----
    ((float4*)(pair + wi))[0] = make_float4(cv.x, dd.x, cv.y, dd.y);
    ((float4*)(pair + wi))[1] = make_float4(cv.z, dd.z, cv.w, dd.w);
    if (hl == 15) pair[64] = make_float2(1.0f, dd.w);   // sentinel (cdf[64], d[64]=d[63])

    // ---- load 8 u's (element index i = hl*8 + m) ----
    const float4* up4 = (const float4*)(rands + (size_t)ray * SF);
    float4 ua = up4[2 * hl], ub = up4[2 * hl + 1];
    float k[8] = {ua.x, ua.y, ua.z, ua.w, ub.x, ub.y, ub.z, ub.w};

    // ---- bitonic sort of 128 u's across 16 lanes x 8 regs ----
    ce(k[0], k[1], true);  ce(k[2], k[3], false);
    ce(k[4], k[5], true);  ce(k[6], k[7], false);
    ce(k[0], k[2], true);  ce(k[1], k[3], true);
    ce(k[0], k[1], true);  ce(k[2], k[3], true);
    ce(k[4], k[6], false); ce(k[5], k[7], false);
    ce(k[4], k[5], false); ce(k[6], k[7], false);
    {
        bool a = (hl & 1) == 0;
        ce(k[0], k[4], a); ce(k[1], k[5], a); ce(k[2], k[6], a); ce(k[3], k[7], a);
        ce(k[0], k[2], a); ce(k[1], k[3], a); ce(k[4], k[6], a); ce(k[5], k[7], a);
        ce(k[0], k[1], a); ce(k[2], k[3], a); ce(k[4], k[5], a); ce(k[6], k[7], a);
    }
    #pragma unroll
    for (int kk = 16; kk <= 128; kk <<= 1) {
        bool a = (hl & (kk >> 3)) == 0;
        #pragma unroll
        for (int L = kk >> 4; L >= 1; L >>= 1) {
            bool dm = (((hl & L) == 0) == a);
            #pragma unroll
            for (int m = 0; m < 8; m++) {
                float p = __shfl_xor_sync(FULL, k[m], L);
                k[m] = dm ? fminf(k[m], p) : fmaxf(k[m], p);
            }
        }
        ce(k[0], k[4], a); ce(k[1], k[5], a); ce(k[2], k[6], a); ce(k[3], k[7], a);
        ce(k[0], k[2], a); ce(k[1], k[3], a); ce(k[4], k[6], a); ce(k[5], k[7], a);
        ce(k[0], k[1], a); ce(k[2], k[3], a); ce(k[4], k[5], a); ce(k[6], k[7], a);
    }
    __syncwarp();   // tables ready

    // ---- search + interp on SORTED u's; scatter; first-occurrence ----
    int prev = -1, idx0 = 0;
    #pragma unroll
    for (int m = 0; m < 8; m++) {
        float u = k[m];
        int idx = (c32 <= u) ? 32 : 0;
        float q2 = idx ? c48 : c16;
        if (q2 <= u) idx += 16;
        float q3 = (idx & 32) ? ((idx & 16) ? c56 : c40)
                              : ((idx & 16) ? c24 : c8);
        if (q3 <= u) idx += 8;
        if (cdfs[idx + 4] <= u) idx += 4;
        if (cdfs[idx + 2] <= u) idx += 2;
        if (cdfs[idx + 1] <= u) idx += 1;
        float2 P0 = pair[idx];
        float2 P1 = pair[idx + 1];
        float den = P1.x - P0.x;
        den = (den < 1e-5f) ? 1.0f : den;
        float t = (u - P0.x) / den;
        float s = fmaf(t, P1.y - P0.y, P0.y);
        s = fminf(s, P1.y);
        obf[hl * 8 + m + idx + 1] = s;           // pos = rank + bin + 1
        if (m == 0) idx0 = idx;
        else if (idx != prev) pref[idx] = hl * 8 + m;
        prev = idx;
    }
    int pb = __shfl_up_sync(FULL, prev, 1);
    if (hl == 0) pb = -1;
    if (idx0 != pb) pref[idx0] = hl * 8;
    __syncwarp();

    // ---- suffix-min over pref[0..63] (4 per lane) ----
    int4 P = ((int4*)pref)[hl];
    int s3 = P.w;
    int s2 = min(P.z, s3);
    int s1 = min(P.y, s2);
    int s0 = min(P.x, s1);
    int S = s0;
    #pragma unroll
    for (int off = 1; off < 16; off <<= 1) {
        int t = __shfl_down_sync(FULL, S, off);
        if (hl + off < 16) S = min(S, t);
    }
    int Sn = __shfl_down_sync(FULL, S, 1);
    if (hl == 15) Sn = 128;
    int f3 = min(s3, Sn);
    int f2 = min(s2, f3);
    int f1 = min(s1, f2);
    int f0 = min(s0, f1);

    // ---- dists: pos = j + prefix[j] ----
    obf[wi     + f0] = dd.x;
    obf[wi + 1 + f1] = dd.y;
    obf[wi + 2 + f2] = dd.z;
    obf[wi + 3 + f3] = dd.w;
    __syncwarp();

    // ---- vectorized coalesced output (both rays contiguous) ----
    const float4* ob4 = (const float4*)out_s[wid][0];
    float4* op4 = (float4*)(out + (size_t)base * NOUT);
    #pragma unroll
    for (int t = 0; t < 3; t++)
        op4[t * 32 + lane] = ob4[t * 32 + lane];
}

extern "C" void kernel_launch(void* const* d_in, const int* in_sizes, int n_in,
                              void* d_out, int out_size) {
    const float* dists   = (const float*)d_in[0];
    const float* weights = (const float*)d_in[1];
    const float* rands   = (const float*)d_in[2];
    float* out = (float*)d_out;
    int B = in_sizes[0] / SC;
    int raysPerBlock = 2 * WPB;
    int blocks = (B + raysPerBlock - 1) / raysPerBlock;
    fine_sample_kernel<<<blocks, 32 * WPB>>>(dists, weights, rands, out, B);
}